// round 13
// baseline (speedup 1.0000x reference)
#include <cuda_runtime.h>
#include <cuda_bf16.h>
#include <cstdint>

#define BB 2
#define MM 2048
#define RR 256
#define HH 16
#define DHH 64
#define DD (HH*DHH)

// Scratch (bf16): q,k in (b,h,m,dh); v TRANSPOSED in (b,h,dh,m).
__device__ __align__(128) __nv_bfloat16 g_q[BB*HH*MM*DHH];
__device__ __align__(128) __nv_bfloat16 g_k[BB*HH*MM*DHH];
__device__ __align__(128) __nv_bfloat16 g_v[BB*HH*MM*DHH];
// RoPE table: per (b*M+m) row, 32 cos then 32 sin.
__device__ __align__(128) float g_cs[BB*MM*64];

// ---------------- misc helpers ----------------
__device__ __forceinline__ uint32_t smem_u32(const void* p) {
    uint32_t a;
    asm("{ .reg .u64 t; cvta.to.shared.u64 t, %1; cvt.u32.u64 %0, t; }" : "=r"(a) : "l"(p));
    return a;
}
__device__ __forceinline__ void cp16(uint32_t dst, const void* src) {
    asm volatile("cp.async.cg.shared.global [%0], [%1], 16;" :: "r"(dst), "l"(src) : "memory");
}
__device__ __forceinline__ void cp_commit() { asm volatile("cp.async.commit_group;" ::: "memory"); }
template <int N>
__device__ __forceinline__ void cp_wait() { asm volatile("cp.async.wait_group %0;" :: "n"(N) : "memory"); }
__device__ __forceinline__ float ex2f(float x) {
    float r;
    asm("ex2.approx.ftz.f32 %0, %1;" : "=f"(r) : "f"(x));
    return r;
}
__device__ __forceinline__ uint32_t bf2(float lo, float hi) {
    __nv_bfloat162 t = __floats2bfloat162_rn(lo, hi);
    return *(uint32_t*)&t;
}
__device__ __forceinline__ uint32_t fbits(float x) { return __float_as_uint(x); }

// m16n8k16 bf16 warp MMA
__device__ __forceinline__ void mmab(float* c, const uint32_t* a, uint32_t b0, uint32_t b1) {
    asm volatile("mma.sync.aligned.m16n8k16.row.col.f32.bf16.bf16.f32 "
        "{%0,%1,%2,%3}, {%4,%5,%6,%7}, {%8,%9}, {%0,%1,%2,%3};"
        : "+f"(c[0]), "+f"(c[1]), "+f"(c[2]), "+f"(c[3])
        : "r"(a[0]), "r"(a[1]), "r"(a[2]), "r"(a[3]), "r"(b0), "r"(b1));
}
// m16n8k8 tf32 warp MMA
__device__ __forceinline__ void mma8(float* c, const uint32_t* a, uint32_t b0, uint32_t b1) {
    asm volatile("mma.sync.aligned.m16n8k8.row.col.f32.tf32.tf32.f32 "
        "{%0,%1,%2,%3}, {%4,%5,%6,%7}, {%8,%9}, {%0,%1,%2,%3};"
        : "+f"(c[0]), "+f"(c[1]), "+f"(c[2]), "+f"(c[3])
        : "r"(a[0]), "r"(a[1]), "r"(a[2]), "r"(a[3]), "r"(b0), "r"(b1));
}
// ldmatrix x4 (sm_75+)
__device__ __forceinline__ void ldm4(uint32_t& r0, uint32_t& r1, uint32_t& r2, uint32_t& r3,
                                     uint32_t addr) {
    asm volatile("ldmatrix.sync.aligned.m8n8.x4.shared.b16 {%0,%1,%2,%3}, [%4];"
        : "=r"(r0), "=r"(r1), "=r"(r2), "=r"(r3) : "r"(addr));
}

// ---------------------------------------------------------------------------
// RoPE table kernel
// ---------------------------------------------------------------------------
__global__ __launch_bounds__(256) void rope_kernel(const int* __restrict__ pos_ids) {
    int idx = blockIdx.x * 256 + threadIdx.x;
    int f = idx & 31, row = idx >> 5;
    float p = (float)pos_ids[row];
    float inv = exp2f(-(float)f * 0.41524101186092033f);
    float s, c;
    sincosf(p * inv, &s, &c);
    g_cs[row * 64 + f] = c;
    g_cs[row * 64 + 32 + f] = s;
}

// ---------------------------------------------------------------------------
// Projection via tf32 mma.sync: 128x128 tile (2 heads) per CTA, 256 threads
// (R11/R12 version, kept).
// ---------------------------------------------------------------------------
#define PA_OFF 0
#define PB_OFF 36864
#define PROJ_SMEM 70656

__global__ __launch_bounds__(256) void proj_kernel(
    const float* __restrict__ Pq, const float* __restrict__ Pk, const float* __restrict__ Pv,
    const float* __restrict__ Vq, const float* __restrict__ Vk, const float* __restrict__ Vv,
    const float* __restrict__ bq, const float* __restrict__ bk, const float* __restrict__ bv)
{
    extern __shared__ char smem[];
    const uint32_t sb = smem_u32(smem);

    const int z = blockIdx.z;
    const float* P    = (z == 0) ? Pq : (z == 1) ? Pk : Pv;
    const float* V    = (z == 0) ? Vq : (z == 1) ? Vk : Vv;
    const float* bias = (z == 0) ? bq : (z == 1) ? bk : bv;
    __nv_bfloat16* dst = (z == 0) ? g_q : (z == 1) ? g_k : g_v;

    const int tid = threadIdx.x;
    const int w = tid >> 5, lane = tid & 31;
    const int g = lane >> 2, tg = lane & 3;
    const int n0 = blockIdx.x * 128;          // 2 heads per CTA
    const int m0 = blockIdx.y * 128;
    const int co = (w >> 2) * 64;             // warp column offset (head select)
    const int wr = (w & 3) * 32;              // warp row offset

    // prologue: chunk 0 into buffer 0
    #pragma unroll
    for (int e = 0; e < 4; e++) {
        int c = e * 256 + tid;
        int row = c >> 3, f = c & 7;
        cp16(sb + PA_OFF + row * 144 + f * 16, P + (size_t)(m0 + row) * RR + f * 4);
    }
    #pragma unroll
    for (int e = 0; e < 4; e++) {
        int c = e * 256 + tid;
        int k = c >> 5, f = c & 31;
        cp16(sb + PB_OFF + k * 528 + f * 16, V + (size_t)k * DD + n0 + f * 4);
    }
    cp_commit();

    float acc[2][8][4];
    #pragma unroll
    for (int gi = 0; gi < 2; gi++)
        #pragma unroll
        for (int j = 0; j < 8; j++)
            #pragma unroll
            for (int c = 0; c < 4; c++) acc[gi][j][c] = 0.0f;

    for (int ch = 0; ch < 8; ch++) {
        const int buf = ch & 1, nb = buf ^ 1;
        if (ch < 7) {
            int k0 = (ch + 1) * 32;
            #pragma unroll
            for (int e = 0; e < 4; e++) {
                int c = e * 256 + tid;
                int row = c >> 3, f = c & 7;
                cp16(sb + PA_OFF + nb * 18432 + row * 144 + f * 16,
                     P + (size_t)(m0 + row) * RR + k0 + f * 4);
            }
            #pragma unroll
            for (int e = 0; e < 4; e++) {
                int c = e * 256 + tid;
                int k = c >> 5, f = c & 31;
                cp16(sb + PB_OFF + nb * 16896 + k * 528 + f * 16,
                     V + (size_t)(k0 + k) * DD + n0 + f * 4);
            }
            cp_commit();
            cp_wait<1>();
        } else {
            cp_wait<0>();
        }
        __syncthreads();

        const float* As  = (const float*)(smem + PA_OFF + buf * 18432);
        const float* Bsm = (const float*)(smem + PB_OFF + buf * 16896);
        #pragma unroll
        for (int s = 0; s < 4; s++) {
            uint32_t a[2][4];
            #pragma unroll
            for (int gi = 0; gi < 2; gi++) {
                int ra = wr + gi * 16 + g;
                a[gi][0] = fbits(As[ra * 36 + 8 * s + tg]);
                a[gi][1] = fbits(As[(ra + 8) * 36 + 8 * s + tg]);
                a[gi][2] = fbits(As[ra * 36 + 8 * s + tg + 4]);
                a[gi][3] = fbits(As[(ra + 8) * 36 + 8 * s + tg + 4]);
            }
            #pragma unroll
            for (int j = 0; j < 8; j++) {
                uint32_t b0 = fbits(Bsm[(8 * s + tg) * 132 + co + 8 * j + g]);
                uint32_t b1 = fbits(Bsm[(8 * s + tg + 4) * 132 + co + 8 * j + g]);
                mma8(acc[0][j], a[0], b0, b1);
                mma8(acc[1][j], a[1], b0, b1);
            }
        }
        __syncthreads();
    }

    if (z == 2) {
        // V: stage 128x128 fp32 (pitch 129) then transposed bf16 store (b,h,dh,m)
        float* stg = (float*)smem;
        #pragma unroll
        for (int gi = 0; gi < 2; gi++) {
            int r0l = wr + gi * 16 + g;
            #pragma unroll
            for (int j = 0; j < 8; j++) {
                int c0 = co + 8 * j + 2 * tg;
                float b0v = bias[n0 + c0], b1v = bias[n0 + c0 + 1];
                stg[r0l * 129 + c0]           = acc[gi][j][0] + b0v;
                stg[r0l * 129 + c0 + 1]       = acc[gi][j][1] + b1v;
                stg[(r0l + 8) * 129 + c0]     = acc[gi][j][2] + b0v;
                stg[(r0l + 8) * 129 + c0 + 1] = acc[gi][j][3] + b1v;
            }
        }
        __syncthreads();
        int c = tid & 127, half = tid >> 7;    // col 0..127, row-half 0/1
        int bb = m0 >> 11, mloc = m0 & (MM - 1);
        int hcol = blockIdx.x * 2 + (c >> 6);
        int dh = c & 63;
        __nv_bfloat16* o = g_v + ((size_t)(bb * HH + hcol) * DHH + dh) * MM + mloc + half * 64;
        #pragma unroll
        for (int e = 0; e < 8; e++) {
            int rb = half * 64 + e * 8;
            uint4 wv;
            wv.x = bf2(stg[rb * 129 + c],       stg[(rb + 1) * 129 + c]);
            wv.y = bf2(stg[(rb + 2) * 129 + c], stg[(rb + 3) * 129 + c]);
            wv.z = bf2(stg[(rb + 4) * 129 + c], stg[(rb + 5) * 129 + c]);
            wv.w = bf2(stg[(rb + 6) * 129 + c], stg[(rb + 7) * 129 + c]);
            *(uint4*)(o + e * 8) = wv;
        }
    } else {
        // q/k: bias + RoPE (table) + bf16 store; warp owns head h
        const int h = blockIdx.x * 2 + (w >> 2);
        const int n0h = h * 64;
        float bl[4][4];
        #pragma unroll
        for (int jlo = 0; jlo < 4; jlo++) {
            int c0 = 8 * jlo + 2 * tg;
            bl[jlo][0] = bias[n0h + c0];
            bl[jlo][1] = bias[n0h + c0 + 1];
            bl[jlo][2] = bias[n0h + c0 + 32];
            bl[jlo][3] = bias[n0h + c0 + 33];
        }
        #pragma unroll
        for (int gi = 0; gi < 2; gi++) {
            int rbase = m0 + wr + gi * 16 + g;
            #pragma unroll
            for (int hh = 0; hh < 2; hh++) {
                int row = rbase + 8 * hh;
                int iA = 2 * hh;
                int bb = row >> 11, mloc = row & (MM - 1);
                const float* cs = g_cs + (size_t)row * 64;
                __nv_bfloat16* o = dst + ((size_t)(bb * HH + h) * MM + mloc) * DHH;
                #pragma unroll
                for (int jlo = 0; jlo < 4; jlo++) {
                    int c0 = 8 * jlo + 2 * tg;
                    float x0a = acc[gi][jlo][iA]         + bl[jlo][0];
                    float x0b = acc[gi][jlo][iA + 1]     + bl[jlo][1];
                    float x1a = acc[gi][jlo + 4][iA]     + bl[jlo][2];
                    float x1b = acc[gi][jlo + 4][iA + 1] + bl[jlo][3];
                    float2 cp = *(const float2*)&cs[c0];
                    float2 sp = *(const float2*)&cs[32 + c0];
                    *(__nv_bfloat162*)&o[c0] =
                        __floats2bfloat162_rn(x0a * cp.x - x1a * sp.x, x0b * cp.y - x1b * sp.y);
                    *(__nv_bfloat162*)&o[c0 + 32] =
                        __floats2bfloat162_rn(x0a * sp.x + x1a * cp.x, x0b * sp.y + x1b * cp.y);
                }
            }
        }
    }
}

// ---------------------------------------------------------------------------
// Attention: R12 base + l-via-ones-MMA (tensor pipe) + anti-phase stagger
// (odd CTAs delay ~1700 cyc so co-resident CTA pairs interleave MUFU vs
// tensor phases instead of phase-locking).
// Smem: Q 18432 | K 2x9216 | Vt 2x9216 | mask 2x256 | maskf 2x256 -> 56320 B
// ---------------------------------------------------------------------------
#define Q_OFF    0
#define K_OFF    18432
#define V_OFF    36864
#define MSK_OFF  55296
#define MSKF_OFF 55808
#define SMEM_TOTAL 56320
#define KV_STRIDE 9216
#define PITCHB 144   // 72 bf16 = 144 bytes per row

__global__ __launch_bounds__(128, 2) void attn_kernel(const int* __restrict__ amask,
                                                      float* __restrict__ out)
{
    extern __shared__ char smem[];
    const uint32_t sb = smem_u32(smem);

    const int tid = threadIdx.x;
    const int w = tid >> 5, lane = tid & 31;
    const int g = lane >> 2, tg = lane & 3;
    const int bh = blockIdx.x;
    const int b = bh >> 4;
    const int m0 = blockIdx.y * 128;

    const float C1 = 0.18033688011112042f;   // (1/8)*log2(e)
    const float C2 = 43.28085122666891f;     // 30*log2(e)
    const uint32_t ONES = 0x3F803F80u;       // bf16x2 (1.0, 1.0)

    // anti-phase stagger: odd CTAs start ~half an iteration late
    if (blockIdx.x & 1) {
        uint64_t t0 = clock64();
        while (clock64() - t0 < 1700) { }
    }

    const __nv_bfloat16* qg = g_q + ((size_t)bh * MM + m0) * DHH;
    const __nv_bfloat16* kg = g_k + (size_t)bh * MM * DHH;
    const __nv_bfloat16* vg = g_v + (size_t)bh * DHH * MM;

    // ---- prologue: Q (128x64), K block0, Vt block0, mask0 ----
    #pragma unroll
    for (int e = 0; e < 8; e++) {
        int c = e * 128 + tid;
        int row = c >> 3, f = c & 7;
        cp16(sb + Q_OFF + row * PITCHB + f * 16, qg + row * 64 + f * 8);
    }
    #pragma unroll
    for (int e = 0; e < 4; e++) {
        int c = e * 128 + tid;
        int row = c >> 3, f = c & 7;
        cp16(sb + K_OFF + row * PITCHB + f * 16, kg + (size_t)row * 64 + f * 8);
        cp16(sb + V_OFF + row * PITCHB + f * 16, vg + (size_t)row * MM + f * 8);
    }
    if (tid < 16) cp16(sb + MSK_OFF + tid * 16, amask + (size_t)b * MM + tid * 4);
    cp_commit();
    cp_wait<0>();
    __syncthreads();
    // mask block0 -> float addend
    if (tid < 64) {
        int mraw = ((const int*)(smem + MSK_OFF))[tid];
        ((float*)(smem + MSKF_OFF))[tid] = mraw ? -C2 : -1e30f;
    }
    __syncthreads();

    // ---- ldmatrix per-thread base offsets ----
    const int lrow = lane & 7, lsel = lane >> 3;
    const uint32_t qbase = sb + Q_OFF
        + (uint32_t)(w * 32 + lrow + (lsel & 1) * 8) * PITCHB + (lsel >> 1) * 16;
    const uint32_t bboff = (uint32_t)(lrow + (lsel >> 1) * 8) * PITCHB + (lsel & 1) * 16;

    float oc[2][8][4];
    #pragma unroll
    for (int gi = 0; gi < 2; gi++)
        #pragma unroll
        for (int j = 0; j < 8; j++)
            #pragma unroll
            for (int c = 0; c < 4; c++) oc[gi][j][c] = 0.0f;
    float lc[2][4];
    #pragma unroll
    for (int gi = 0; gi < 2; gi++)
        #pragma unroll
        for (int c = 0; c < 4; c++) lc[gi][c] = 0.0f;

    const int row0 = w * 32;

    for (int i = 0; i < 32; i++) {
        const int buf = i & 1, nb = buf ^ 1;

        if (i < 31) {
            int n1 = (i + 1) * 64;
            #pragma unroll
            for (int e = 0; e < 4; e++) {
                int c = e * 128 + tid;
                int row = c >> 3, f = c & 7;
                cp16(sb + K_OFF + nb * KV_STRIDE + row * PITCHB + f * 16,
                     kg + (size_t)(n1 + row) * 64 + f * 8);
                cp16(sb + V_OFF + nb * KV_STRIDE + row * PITCHB + f * 16,
                     vg + (size_t)row * MM + n1 + f * 8);
            }
            if (tid < 16) cp16(sb + MSK_OFF + nb * 256 + tid * 16,
                               amask + (size_t)b * MM + n1 + tid * 4);
            cp_commit();
        }

        const uint32_t kb = sb + K_OFF + buf * KV_STRIDE + bboff;
        const uint32_t vb = sb + V_OFF + buf * KV_STRIDE + bboff;
        const float* mskf = (const float*)(smem + MSKF_OFF + buf * 256);

        // ---- S = Q(32 rows) x K^T(64 keys), frags via ldmatrix ----
        float sc[2][8][4];
        #pragma unroll
        for (int gi = 0; gi < 2; gi++)
            #pragma unroll
            for (int j = 0; j < 8; j++)
                #pragma unroll
                for (int c = 0; c < 4; c++) sc[gi][j][c] = 0.0f;

        #pragma unroll
        for (int s = 0; s < 4; s++) {
            uint32_t a[2][4];
            ldm4(a[0][0], a[0][1], a[0][2], a[0][3], qbase + s * 32);
            ldm4(a[1][0], a[1][1], a[1][2], a[1][3], qbase + 16 * PITCHB + s * 32);
            #pragma unroll
            for (int jp = 0; jp < 4; jp++) {
                uint32_t b0, b1, b2, b3;
                ldm4(b0, b1, b2, b3, kb + jp * (16 * PITCHB) + s * 32);
                mmab(sc[0][2 * jp],     a[0], b0, b1);
                mmab(sc[1][2 * jp],     a[1], b0, b1);
                mmab(sc[0][2 * jp + 1], a[0], b2, b3);
                mmab(sc[1][2 * jp + 1], a[1], b2, b3);
            }
        }

        // ---- softmax: p = ex2(fma(s, C1, maskf)); pack into A-frags ----
        uint32_t pa[2][4][4];
        #pragma unroll
        for (int j = 0; j < 8; j++) {
            float2 mf = *(const float2*)&mskf[8 * j + 2 * tg];
            #pragma unroll
            for (int gi = 0; gi < 2; gi++) {
                float p0 = ex2f(fmaf(sc[gi][j][0], C1, mf.x));
                float p1 = ex2f(fmaf(sc[gi][j][1], C1, mf.y));
                float p2 = ex2f(fmaf(sc[gi][j][2], C1, mf.x));
                float p3 = ex2f(fmaf(sc[gi][j][3], C1, mf.y));
                int s = j >> 1;
                if ((j & 1) == 0) {
                    pa[gi][s][0] = bf2(p0, p1);
                    pa[gi][s][1] = bf2(p2, p3);
                } else {
                    pa[gi][s][2] = bf2(p0, p1);
                    pa[gi][s][3] = bf2(p2, p3);
                }
            }
        }

        // ---- O += P x V ; l += P x ones (tensor pipe) ----
        #pragma unroll
        for (int s = 0; s < 4; s++) {
            #pragma unroll
            for (int jp = 0; jp < 4; jp++) {
                uint32_t b0, b1, b2, b3;
                ldm4(b0, b1, b2, b3, vb + jp * (16 * PITCHB) + s * 32);
                mmab(oc[0][2 * jp],     pa[0][s], b0, b1);
                mmab(oc[1][2 * jp],     pa[1][s], b0, b1);
                mmab(oc[0][2 * jp + 1], pa[0][s], b2, b3);
                mmab(oc[1][2 * jp + 1], pa[1][s], b2, b3);
            }
            mmab(lc[0], pa[0][s], ONES, ONES);
            mmab(lc[1], pa[1][s], ONES, ONES);
        }

        cp_wait<0>();
        // convert next mask block (its cp.async completed just above)
        if (i < 31 && tid < 64) {
            int mraw = ((const int*)(smem + MSK_OFF + nb * 256))[tid];
            ((float*)(smem + MSKF_OFF + nb * 256))[tid] = mraw ? -C2 : -1e30f;
        }
        __syncthreads();
    }

    // ---- finalize: l comes straight from the ones-MMA accumulator ----
    #pragma unroll
    for (int gi = 0; gi < 2; gi++) {
        float l0 = lc[gi][0];
        float l1 = lc[gi][2];
        float i0 = (l0 > 0.f) ? (1.0f / l0) : 0.f;
        float i1 = (l1 > 0.f) ? (1.0f / l1) : 0.f;
        int row = row0 + gi * 16 + g;
        float* o0 = out + ((size_t)bh * MM + m0 + row) * DHH;
        float* o1 = out + ((size_t)bh * MM + m0 + row + 8) * DHH;
        #pragma unroll
        for (int j = 0; j < 8; j++) {
            *(float2*)(o0 + 8 * j + 2 * tg) = make_float2(oc[gi][j][0] * i0, oc[gi][j][1] * i0);
            *(float2*)(o1 + 8 * j + 2 * tg) = make_float2(oc[gi][j][2] * i1, oc[gi][j][3] * i1);
        }
    }
}

extern "C" void kernel_launch(void* const* d_in, const int* in_sizes, int n_in,
                              void* d_out, int out_size) {
    const float* Pq = (const float*)d_in[0];
    const float* Pk = (const float*)d_in[1];
    const float* Pv = (const float*)d_in[2];
    const float* Vq = (const float*)d_in[3];
    const float* Vk = (const float*)d_in[4];
    const float* Vv = (const float*)d_in[5];
    const float* bq = (const float*)d_in[6];
    const float* bk = (const float*)d_in[7];
    const float* bv = (const float*)d_in[8];
    const int* amask = (const int*)d_in[9];
    const int* pos   = (const int*)d_in[10];

    static int smem_set = 0;
    if (!smem_set) {
        cudaFuncSetAttribute(attn_kernel, cudaFuncAttributeMaxDynamicSharedMemorySize, SMEM_TOTAL);
        cudaFuncSetAttribute(proj_kernel, cudaFuncAttributeMaxDynamicSharedMemorySize, PROJ_SMEM);
        smem_set = 1;
    }

    rope_kernel<<<BB * MM * 32 / 256, 256>>>(pos);

    dim3 pg(HH / 2, (BB * MM) / 128, 3);     // 8 x 32 x 3
    proj_kernel<<<pg, 256, PROJ_SMEM>>>(Pq, Pk, Pv, Vq, Vk, Vv, bq, bk, bv);

    dim3 ag(BB * HH, MM / 128);              // 32 x 16
    attn_kernel<<<ag, 128, SMEM_TOTAL>>>(amask, (float*)d_out);
}

// round 14
// speedup vs baseline: 1.0209x; 1.0209x over previous
#include <cuda_runtime.h>
#include <cuda_bf16.h>
#include <cstdint>

#define BB 2
#define MM 2048
#define RR 256
#define HH 16
#define DHH 64
#define DD (HH*DHH)

// Scratch (bf16): q,k in (b,h,m,dh); v TRANSPOSED in (b,h,dh,m).
__device__ __align__(128) __nv_bfloat16 g_q[BB*HH*MM*DHH];
__device__ __align__(128) __nv_bfloat16 g_k[BB*HH*MM*DHH];
__device__ __align__(128) __nv_bfloat16 g_v[BB*HH*MM*DHH];
// RoPE table: per (b*M+m) row, 32 cos then 32 sin.
__device__ __align__(128) float g_cs[BB*MM*64];

// ---------------- misc helpers ----------------
__device__ __forceinline__ uint32_t smem_u32(const void* p) {
    uint32_t a;
    asm("{ .reg .u64 t; cvta.to.shared.u64 t, %1; cvt.u32.u64 %0, t; }" : "=r"(a) : "l"(p));
    return a;
}
__device__ __forceinline__ void cp16(uint32_t dst, const void* src) {
    asm volatile("cp.async.cg.shared.global [%0], [%1], 16;" :: "r"(dst), "l"(src) : "memory");
}
__device__ __forceinline__ void cp_commit() { asm volatile("cp.async.commit_group;" ::: "memory"); }
template <int N>
__device__ __forceinline__ void cp_wait() { asm volatile("cp.async.wait_group %0;" :: "n"(N) : "memory"); }
__device__ __forceinline__ float ex2f(float x) {
    float r;
    asm("ex2.approx.ftz.f32 %0, %1;" : "=f"(r) : "f"(x));
    return r;
}
__device__ __forceinline__ uint32_t bf2(float lo, float hi) {
    __nv_bfloat162 t = __floats2bfloat162_rn(lo, hi);
    return *(uint32_t*)&t;
}
__device__ __forceinline__ uint32_t fbits(float x) { return __float_as_uint(x); }

// m16n8k16 bf16 warp MMA
__device__ __forceinline__ void mmab(float* c, const uint32_t* a, uint32_t b0, uint32_t b1) {
    asm volatile("mma.sync.aligned.m16n8k16.row.col.f32.bf16.bf16.f32 "
        "{%0,%1,%2,%3}, {%4,%5,%6,%7}, {%8,%9}, {%0,%1,%2,%3};"
        : "+f"(c[0]), "+f"(c[1]), "+f"(c[2]), "+f"(c[3])
        : "r"(a[0]), "r"(a[1]), "r"(a[2]), "r"(a[3]), "r"(b0), "r"(b1));
}
// m16n8k8 tf32 warp MMA
__device__ __forceinline__ void mma8(float* c, const uint32_t* a, uint32_t b0, uint32_t b1) {
    asm volatile("mma.sync.aligned.m16n8k8.row.col.f32.tf32.tf32.f32 "
        "{%0,%1,%2,%3}, {%4,%5,%6,%7}, {%8,%9}, {%0,%1,%2,%3};"
        : "+f"(c[0]), "+f"(c[1]), "+f"(c[2]), "+f"(c[3])
        : "r"(a[0]), "r"(a[1]), "r"(a[2]), "r"(a[3]), "r"(b0), "r"(b1));
}
// ldmatrix x4 (sm_75+)
__device__ __forceinline__ void ldm4(uint32_t& r0, uint32_t& r1, uint32_t& r2, uint32_t& r3,
                                     uint32_t addr) {
    asm volatile("ldmatrix.sync.aligned.m8n8.x4.shared.b16 {%0,%1,%2,%3}, [%4];"
        : "=r"(r0), "=r"(r1), "=r"(r2), "=r"(r3) : "r"(addr));
}

// ---------------------------------------------------------------------------
// RoPE table kernel
// ---------------------------------------------------------------------------
__global__ __launch_bounds__(256) void rope_kernel(const int* __restrict__ pos_ids) {
    int idx = blockIdx.x * 256 + threadIdx.x;
    int f = idx & 31, row = idx >> 5;
    float p = (float)pos_ids[row];
    float inv = exp2f(-(float)f * 0.41524101186092033f);
    float s, c;
    sincosf(p * inv, &s, &c);
    g_cs[row * 64 + f] = c;
    g_cs[row * 64 + 32 + f] = s;
}

// ---------------------------------------------------------------------------
// Projection via tf32 mma.sync: 128x128 tile (2 heads) per CTA, 256 threads.
// __launch_bounds__(256, 2) forces regs <= 125 so TWO CTAs co-reside per SM
// (without the hint ptxas exceeds the 2-CTA register budget and occupancy
// silently halves -> 5.2 serial waves instead of 2.6).
// ---------------------------------------------------------------------------
#define PA_OFF 0
#define PB_OFF 36864
#define PROJ_SMEM 70656

__global__ __launch_bounds__(256, 2) void proj_kernel(
    const float* __restrict__ Pq, const float* __restrict__ Pk, const float* __restrict__ Pv,
    const float* __restrict__ Vq, const float* __restrict__ Vk, const float* __restrict__ Vv,
    const float* __restrict__ bq, const float* __restrict__ bk, const float* __restrict__ bv)
{
    extern __shared__ char smem[];
    const uint32_t sb = smem_u32(smem);

    const int z = blockIdx.z;
    const float* P    = (z == 0) ? Pq : (z == 1) ? Pk : Pv;
    const float* V    = (z == 0) ? Vq : (z == 1) ? Vk : Vv;
    const float* bias = (z == 0) ? bq : (z == 1) ? bk : bv;
    __nv_bfloat16* dst = (z == 0) ? g_q : (z == 1) ? g_k : g_v;

    const int tid = threadIdx.x;
    const int w = tid >> 5, lane = tid & 31;
    const int g = lane >> 2, tg = lane & 3;
    const int n0 = blockIdx.x * 128;          // 2 heads per CTA
    const int m0 = blockIdx.y * 128;
    const int co = (w >> 2) * 64;             // warp column offset (head select)
    const int wr = (w & 3) * 32;              // warp row offset

    // prologue: chunk 0 into buffer 0
    #pragma unroll
    for (int e = 0; e < 4; e++) {
        int c = e * 256 + tid;
        int row = c >> 3, f = c & 7;
        cp16(sb + PA_OFF + row * 144 + f * 16, P + (size_t)(m0 + row) * RR + f * 4);
    }
    #pragma unroll
    for (int e = 0; e < 4; e++) {
        int c = e * 256 + tid;
        int k = c >> 5, f = c & 31;
        cp16(sb + PB_OFF + k * 528 + f * 16, V + (size_t)k * DD + n0 + f * 4);
    }
    cp_commit();

    float acc[2][8][4];
    #pragma unroll
    for (int gi = 0; gi < 2; gi++)
        #pragma unroll
        for (int j = 0; j < 8; j++)
            #pragma unroll
            for (int c = 0; c < 4; c++) acc[gi][j][c] = 0.0f;

    for (int ch = 0; ch < 8; ch++) {
        const int buf = ch & 1, nb = buf ^ 1;
        if (ch < 7) {
            int k0 = (ch + 1) * 32;
            #pragma unroll
            for (int e = 0; e < 4; e++) {
                int c = e * 256 + tid;
                int row = c >> 3, f = c & 7;
                cp16(sb + PA_OFF + nb * 18432 + row * 144 + f * 16,
                     P + (size_t)(m0 + row) * RR + k0 + f * 4);
            }
            #pragma unroll
            for (int e = 0; e < 4; e++) {
                int c = e * 256 + tid;
                int k = c >> 5, f = c & 31;
                cp16(sb + PB_OFF + nb * 16896 + k * 528 + f * 16,
                     V + (size_t)(k0 + k) * DD + n0 + f * 4);
            }
            cp_commit();
            cp_wait<1>();
        } else {
            cp_wait<0>();
        }
        __syncthreads();

        const float* As  = (const float*)(smem + PA_OFF + buf * 18432);
        const float* Bsm = (const float*)(smem + PB_OFF + buf * 16896);
        #pragma unroll
        for (int s = 0; s < 4; s++) {
            uint32_t a[2][4];
            #pragma unroll
            for (int gi = 0; gi < 2; gi++) {
                int ra = wr + gi * 16 + g;
                a[gi][0] = fbits(As[ra * 36 + 8 * s + tg]);
                a[gi][1] = fbits(As[(ra + 8) * 36 + 8 * s + tg]);
                a[gi][2] = fbits(As[ra * 36 + 8 * s + tg + 4]);
                a[gi][3] = fbits(As[(ra + 8) * 36 + 8 * s + tg + 4]);
            }
            #pragma unroll
            for (int j = 0; j < 8; j++) {
                uint32_t b0 = fbits(Bsm[(8 * s + tg) * 132 + co + 8 * j + g]);
                uint32_t b1 = fbits(Bsm[(8 * s + tg + 4) * 132 + co + 8 * j + g]);
                mma8(acc[0][j], a[0], b0, b1);
                mma8(acc[1][j], a[1], b0, b1);
            }
        }
        __syncthreads();
    }

    if (z == 2) {
        // V: stage 128x128 fp32 (pitch 129) then transposed bf16 store (b,h,dh,m)
        float* stg = (float*)smem;
        #pragma unroll
        for (int gi = 0; gi < 2; gi++) {
            int r0l = wr + gi * 16 + g;
            #pragma unroll
            for (int j = 0; j < 8; j++) {
                int c0 = co + 8 * j + 2 * tg;
                float b0v = bias[n0 + c0], b1v = bias[n0 + c0 + 1];
                stg[r0l * 129 + c0]           = acc[gi][j][0] + b0v;
                stg[r0l * 129 + c0 + 1]       = acc[gi][j][1] + b1v;
                stg[(r0l + 8) * 129 + c0]     = acc[gi][j][2] + b0v;
                stg[(r0l + 8) * 129 + c0 + 1] = acc[gi][j][3] + b1v;
            }
        }
        __syncthreads();
        int c = tid & 127, half = tid >> 7;    // col 0..127, row-half 0/1
        int bb = m0 >> 11, mloc = m0 & (MM - 1);
        int hcol = blockIdx.x * 2 + (c >> 6);
        int dh = c & 63;
        __nv_bfloat16* o = g_v + ((size_t)(bb * HH + hcol) * DHH + dh) * MM + mloc + half * 64;
        #pragma unroll
        for (int e = 0; e < 8; e++) {
            int rb = half * 64 + e * 8;
            uint4 wv;
            wv.x = bf2(stg[rb * 129 + c],       stg[(rb + 1) * 129 + c]);
            wv.y = bf2(stg[(rb + 2) * 129 + c], stg[(rb + 3) * 129 + c]);
            wv.z = bf2(stg[(rb + 4) * 129 + c], stg[(rb + 5) * 129 + c]);
            wv.w = bf2(stg[(rb + 6) * 129 + c], stg[(rb + 7) * 129 + c]);
            *(uint4*)(o + e * 8) = wv;
        }
    } else {
        // q/k: bias + RoPE (table) + bf16 store; warp owns head h
        const int h = blockIdx.x * 2 + (w >> 2);
        const int n0h = h * 64;
        float bl[4][4];
        #pragma unroll
        for (int jlo = 0; jlo < 4; jlo++) {
            int c0 = 8 * jlo + 2 * tg;
            bl[jlo][0] = bias[n0h + c0];
            bl[jlo][1] = bias[n0h + c0 + 1];
            bl[jlo][2] = bias[n0h + c0 + 32];
            bl[jlo][3] = bias[n0h + c0 + 33];
        }
        #pragma unroll
        for (int gi = 0; gi < 2; gi++) {
            int rbase = m0 + wr + gi * 16 + g;
            #pragma unroll
            for (int hh = 0; hh < 2; hh++) {
                int row = rbase + 8 * hh;
                int iA = 2 * hh;
                int bb = row >> 11, mloc = row & (MM - 1);
                const float* cs = g_cs + (size_t)row * 64;
                __nv_bfloat16* o = dst + ((size_t)(bb * HH + h) * MM + mloc) * DHH;
                #pragma unroll
                for (int jlo = 0; jlo < 4; jlo++) {
                    int c0 = 8 * jlo + 2 * tg;
                    float x0a = acc[gi][jlo][iA]         + bl[jlo][0];
                    float x0b = acc[gi][jlo][iA + 1]     + bl[jlo][1];
                    float x1a = acc[gi][jlo + 4][iA]     + bl[jlo][2];
                    float x1b = acc[gi][jlo + 4][iA + 1] + bl[jlo][3];
                    float2 cp = *(const float2*)&cs[c0];
                    float2 sp = *(const float2*)&cs[32 + c0];
                    *(__nv_bfloat162*)&o[c0] =
                        __floats2bfloat162_rn(x0a * cp.x - x1a * sp.x, x0b * cp.y - x1b * sp.y);
                    *(__nv_bfloat162*)&o[c0 + 32] =
                        __floats2bfloat162_rn(x0a * sp.x + x1a * cp.x, x0b * sp.y + x1b * cp.y);
                }
            }
        }
    }
}

// ---------------------------------------------------------------------------
// Attention: R12 version verbatim (bf16 m16n8k16, ldmatrix frags, register P,
// mask-addend softmax, scalar l accumulation, 128 thr, 2 CTAs/SM).
// Smem: Q 18432 | K 2x9216 | Vt 2x9216 | mask 2x256 | maskf 2x256 -> 56320 B
// ---------------------------------------------------------------------------
#define Q_OFF    0
#define K_OFF    18432
#define V_OFF    36864
#define MSK_OFF  55296
#define MSKF_OFF 55808
#define SMEM_TOTAL 56320
#define KV_STRIDE 9216
#define PITCHB 144   // 72 bf16 = 144 bytes per row

__global__ __launch_bounds__(128, 2) void attn_kernel(const int* __restrict__ amask,
                                                      float* __restrict__ out)
{
    extern __shared__ char smem[];
    const uint32_t sb = smem_u32(smem);

    const int tid = threadIdx.x;
    const int w = tid >> 5, lane = tid & 31;
    const int g = lane >> 2, tg = lane & 3;
    const int bh = blockIdx.x;
    const int b = bh >> 4;
    const int m0 = blockIdx.y * 128;

    const float C1 = 0.18033688011112042f;   // (1/8)*log2(e)
    const float C2 = 43.28085122666891f;     // 30*log2(e)

    const __nv_bfloat16* qg = g_q + ((size_t)bh * MM + m0) * DHH;
    const __nv_bfloat16* kg = g_k + (size_t)bh * MM * DHH;
    const __nv_bfloat16* vg = g_v + (size_t)bh * DHH * MM;

    // ---- prologue: Q (128x64), K block0, Vt block0, mask0 ----
    #pragma unroll
    for (int e = 0; e < 8; e++) {
        int c = e * 128 + tid;
        int row = c >> 3, f = c & 7;
        cp16(sb + Q_OFF + row * PITCHB + f * 16, qg + row * 64 + f * 8);
    }
    #pragma unroll
    for (int e = 0; e < 4; e++) {
        int c = e * 128 + tid;
        int row = c >> 3, f = c & 7;
        cp16(sb + K_OFF + row * PITCHB + f * 16, kg + (size_t)row * 64 + f * 8);
        cp16(sb + V_OFF + row * PITCHB + f * 16, vg + (size_t)row * MM + f * 8);
    }
    if (tid < 16) cp16(sb + MSK_OFF + tid * 16, amask + (size_t)b * MM + tid * 4);
    cp_commit();
    cp_wait<0>();
    __syncthreads();
    // mask block0 -> float addend
    if (tid < 64) {
        int mraw = ((const int*)(smem + MSK_OFF))[tid];
        ((float*)(smem + MSKF_OFF))[tid] = mraw ? -C2 : -1e30f;
    }
    __syncthreads();

    // ---- ldmatrix per-thread base offsets ----
    const int lrow = lane & 7, lsel = lane >> 3;
    const uint32_t qbase = sb + Q_OFF
        + (uint32_t)(w * 32 + lrow + (lsel & 1) * 8) * PITCHB + (lsel >> 1) * 16;
    const uint32_t bboff = (uint32_t)(lrow + (lsel >> 1) * 8) * PITCHB + (lsel & 1) * 16;

    float oc[2][8][4];
    #pragma unroll
    for (int gi = 0; gi < 2; gi++)
        #pragma unroll
        for (int j = 0; j < 8; j++)
            #pragma unroll
            for (int c = 0; c < 4; c++) oc[gi][j][c] = 0.0f;
    float ls[2][2] = {{0.f, 0.f}, {0.f, 0.f}};

    const int row0 = w * 32;

    for (int i = 0; i < 32; i++) {
        const int buf = i & 1, nb = buf ^ 1;

        if (i < 31) {
            int n1 = (i + 1) * 64;
            #pragma unroll
            for (int e = 0; e < 4; e++) {
                int c = e * 128 + tid;
                int row = c >> 3, f = c & 7;
                cp16(sb + K_OFF + nb * KV_STRIDE + row * PITCHB + f * 16,
                     kg + (size_t)(n1 + row) * 64 + f * 8);
                cp16(sb + V_OFF + nb * KV_STRIDE + row * PITCHB + f * 16,
                     vg + (size_t)row * MM + n1 + f * 8);
            }
            if (tid < 16) cp16(sb + MSK_OFF + nb * 256 + tid * 16,
                               amask + (size_t)b * MM + n1 + tid * 4);
            cp_commit();
        }

        const uint32_t kb = sb + K_OFF + buf * KV_STRIDE + bboff;
        const uint32_t vb = sb + V_OFF + buf * KV_STRIDE + bboff;
        const float* mskf = (const float*)(smem + MSKF_OFF + buf * 256);

        // ---- S = Q(32 rows) x K^T(64 keys), frags via ldmatrix ----
        float sc[2][8][4];
        #pragma unroll
        for (int gi = 0; gi < 2; gi++)
            #pragma unroll
            for (int j = 0; j < 8; j++)
                #pragma unroll
                for (int c = 0; c < 4; c++) sc[gi][j][c] = 0.0f;

        #pragma unroll
        for (int s = 0; s < 4; s++) {
            uint32_t a[2][4];
            ldm4(a[0][0], a[0][1], a[0][2], a[0][3], qbase + s * 32);
            ldm4(a[1][0], a[1][1], a[1][2], a[1][3], qbase + 16 * PITCHB + s * 32);
            #pragma unroll
            for (int jp = 0; jp < 4; jp++) {
                uint32_t b0, b1, b2, b3;
                ldm4(b0, b1, b2, b3, kb + jp * (16 * PITCHB) + s * 32);
                mmab(sc[0][2 * jp],     a[0], b0, b1);
                mmab(sc[1][2 * jp],     a[1], b0, b1);
                mmab(sc[0][2 * jp + 1], a[0], b2, b3);
                mmab(sc[1][2 * jp + 1], a[1], b2, b3);
            }
        }

        // ---- softmax: p = ex2(fma(s, C1, maskf)); pack into A-frags ----
        uint32_t pa[2][4][4];
        #pragma unroll
        for (int j = 0; j < 8; j++) {
            float2 mf = *(const float2*)&mskf[8 * j + 2 * tg];
            #pragma unroll
            for (int gi = 0; gi < 2; gi++) {
                float p0 = ex2f(fmaf(sc[gi][j][0], C1, mf.x));
                float p1 = ex2f(fmaf(sc[gi][j][1], C1, mf.y));
                float p2 = ex2f(fmaf(sc[gi][j][2], C1, mf.x));
                float p3 = ex2f(fmaf(sc[gi][j][3], C1, mf.y));
                ls[gi][0] += p0 + p1;
                ls[gi][1] += p2 + p3;
                int s = j >> 1;
                if ((j & 1) == 0) {
                    pa[gi][s][0] = bf2(p0, p1);
                    pa[gi][s][1] = bf2(p2, p3);
                } else {
                    pa[gi][s][2] = bf2(p0, p1);
                    pa[gi][s][3] = bf2(p2, p3);
                }
            }
        }

        // ---- O += P x V (B frags via ldmatrix) ----
        #pragma unroll
        for (int s = 0; s < 4; s++) {
            #pragma unroll
            for (int jp = 0; jp < 4; jp++) {
                uint32_t b0, b1, b2, b3;
                ldm4(b0, b1, b2, b3, vb + jp * (16 * PITCHB) + s * 32);
                mmab(oc[0][2 * jp],     pa[0][s], b0, b1);
                mmab(oc[1][2 * jp],     pa[1][s], b0, b1);
                mmab(oc[0][2 * jp + 1], pa[0][s], b2, b3);
                mmab(oc[1][2 * jp + 1], pa[1][s], b2, b3);
            }
        }

        cp_wait<0>();
        // convert next mask block (its cp.async completed just above)
        if (i < 31 && tid < 64) {
            int mraw = ((const int*)(smem + MSK_OFF + nb * 256))[tid];
            ((float*)(smem + MSKF_OFF + nb * 256))[tid] = mraw ? -C2 : -1e30f;
        }
        __syncthreads();
    }

    // ---- finalize ----
    #pragma unroll
    for (int gi = 0; gi < 2; gi++) {
        float l0 = ls[gi][0];
        l0 += __shfl_xor_sync(0xffffffffu, l0, 1);
        l0 += __shfl_xor_sync(0xffffffffu, l0, 2);
        float l1 = ls[gi][1];
        l1 += __shfl_xor_sync(0xffffffffu, l1, 1);
        l1 += __shfl_xor_sync(0xffffffffu, l1, 2);
        float i0 = (l0 > 0.f) ? (1.0f / l0) : 0.f;
        float i1 = (l1 > 0.f) ? (1.0f / l1) : 0.f;
        int row = row0 + gi * 16 + g;
        float* o0 = out + ((size_t)bh * MM + m0 + row) * DHH;
        float* o1 = out + ((size_t)bh * MM + m0 + row + 8) * DHH;
        #pragma unroll
        for (int j = 0; j < 8; j++) {
            *(float2*)(o0 + 8 * j + 2 * tg) = make_float2(oc[gi][j][0] * i0, oc[gi][j][1] * i0);
            *(float2*)(o1 + 8 * j + 2 * tg) = make_float2(oc[gi][j][2] * i1, oc[gi][j][3] * i1);
        }
    }
}

extern "C" void kernel_launch(void* const* d_in, const int* in_sizes, int n_in,
                              void* d_out, int out_size) {
    const float* Pq = (const float*)d_in[0];
    const float* Pk = (const float*)d_in[1];
    const float* Pv = (const float*)d_in[2];
    const float* Vq = (const float*)d_in[3];
    const float* Vk = (const float*)d_in[4];
    const float* Vv = (const float*)d_in[5];
    const float* bq = (const float*)d_in[6];
    const float* bk = (const float*)d_in[7];
    const float* bv = (const float*)d_in[8];
    const int* amask = (const int*)d_in[9];
    const int* pos   = (const int*)d_in[10];

    static int smem_set = 0;
    if (!smem_set) {
        cudaFuncSetAttribute(attn_kernel, cudaFuncAttributeMaxDynamicSharedMemorySize, SMEM_TOTAL);
        cudaFuncSetAttribute(proj_kernel, cudaFuncAttributeMaxDynamicSharedMemorySize, PROJ_SMEM);
        smem_set = 1;
    }

    rope_kernel<<<BB * MM * 32 / 256, 256>>>(pos);

    dim3 pg(HH / 2, (BB * MM) / 128, 3);     // 8 x 32 x 3
    proj_kernel<<<pg, 256, PROJ_SMEM>>>(Pq, Pk, Pv, Vq, Vk, Vv, bq, bk, bv);

    dim3 ag(BB * HH, MM / 128);              // 32 x 16
    attn_kernel<<<ag, 128, SMEM_TOTAL>>>(amask, (float*)d_out);
}

// round 15
// speedup vs baseline: 1.0448x; 1.0235x over previous
#include <cuda_runtime.h>
#include <cuda_bf16.h>
#include <cstdint>

#define BB 2
#define MM 2048
#define RR 256
#define HH 16
#define DHH 64
#define DD (HH*DHH)

// Scratch (bf16): q,k in (b,h,m,dh); v TRANSPOSED in (b,h,dh,m).
__device__ __align__(128) __nv_bfloat16 g_q[BB*HH*MM*DHH];
__device__ __align__(128) __nv_bfloat16 g_k[BB*HH*MM*DHH];
__device__ __align__(128) __nv_bfloat16 g_v[BB*HH*MM*DHH];
// RoPE table: per (b*M+m) row, 32 cos then 32 sin.
__device__ __align__(128) float g_cs[BB*MM*64];

// ---------------- misc helpers ----------------
__device__ __forceinline__ uint32_t smem_u32(const void* p) {
    uint32_t a;
    asm("{ .reg .u64 t; cvta.to.shared.u64 t, %1; cvt.u32.u64 %0, t; }" : "=r"(a) : "l"(p));
    return a;
}
__device__ __forceinline__ void cp16(uint32_t dst, const void* src) {
    asm volatile("cp.async.cg.shared.global [%0], [%1], 16;" :: "r"(dst), "l"(src) : "memory");
}
__device__ __forceinline__ void cp_commit() { asm volatile("cp.async.commit_group;" ::: "memory"); }
template <int N>
__device__ __forceinline__ void cp_wait() { asm volatile("cp.async.wait_group %0;" :: "n"(N) : "memory"); }
__device__ __forceinline__ float ex2f(float x) {
    float r;
    asm("ex2.approx.ftz.f32 %0, %1;" : "=f"(r) : "f"(x));
    return r;
}
__device__ __forceinline__ uint32_t bf2(float lo, float hi) {
    __nv_bfloat162 t = __floats2bfloat162_rn(lo, hi);
    return *(uint32_t*)&t;
}
__device__ __forceinline__ uint32_t fbits(float x) { return __float_as_uint(x); }

// m16n8k16 bf16 warp MMA
__device__ __forceinline__ void mmab(float* c, const uint32_t* a, uint32_t b0, uint32_t b1) {
    asm volatile("mma.sync.aligned.m16n8k16.row.col.f32.bf16.bf16.f32 "
        "{%0,%1,%2,%3}, {%4,%5,%6,%7}, {%8,%9}, {%0,%1,%2,%3};"
        : "+f"(c[0]), "+f"(c[1]), "+f"(c[2]), "+f"(c[3])
        : "r"(a[0]), "r"(a[1]), "r"(a[2]), "r"(a[3]), "r"(b0), "r"(b1));
}
// m16n8k8 tf32 warp MMA
__device__ __forceinline__ void mma8(float* c, const uint32_t* a, uint32_t b0, uint32_t b1) {
    asm volatile("mma.sync.aligned.m16n8k8.row.col.f32.tf32.tf32.f32 "
        "{%0,%1,%2,%3}, {%4,%5,%6,%7}, {%8,%9}, {%0,%1,%2,%3};"
        : "+f"(c[0]), "+f"(c[1]), "+f"(c[2]), "+f"(c[3])
        : "r"(a[0]), "r"(a[1]), "r"(a[2]), "r"(a[3]), "r"(b0), "r"(b1));
}
// ldmatrix x4 (sm_75+)
__device__ __forceinline__ void ldm4(uint32_t& r0, uint32_t& r1, uint32_t& r2, uint32_t& r3,
                                     uint32_t addr) {
    asm volatile("ldmatrix.sync.aligned.m8n8.x4.shared.b16 {%0,%1,%2,%3}, [%4];"
        : "=r"(r0), "=r"(r1), "=r"(r2), "=r"(r3) : "r"(addr));
}

// ---------------------------------------------------------------------------
// RoPE table kernel
// ---------------------------------------------------------------------------
__global__ __launch_bounds__(256) void rope_kernel(const int* __restrict__ pos_ids) {
    int idx = blockIdx.x * 256 + threadIdx.x;
    int f = idx & 31, row = idx >> 5;
    float p = (float)pos_ids[row];
    float inv = exp2f(-(float)f * 0.41524101186092033f);
    float s, c;
    sincosf(p * inv, &s, &c);
    g_cs[row * 64 + f] = c;
    g_cs[row * 64 + 32 + f] = s;
}

// ---------------------------------------------------------------------------
// Projection via tf32 mma.sync: 128x128 tile (2 heads) per CTA, 256 threads
// (exact R12 version — no minBlocks hint).
// ---------------------------------------------------------------------------
#define PA_OFF 0
#define PB_OFF 36864
#define PROJ_SMEM 70656

__global__ __launch_bounds__(256) void proj_kernel(
    const float* __restrict__ Pq, const float* __restrict__ Pk, const float* __restrict__ Pv,
    const float* __restrict__ Vq, const float* __restrict__ Vk, const float* __restrict__ Vv,
    const float* __restrict__ bq, const float* __restrict__ bk, const float* __restrict__ bv)
{
    extern __shared__ char smem[];
    const uint32_t sb = smem_u32(smem);

    const int z = blockIdx.z;
    const float* P    = (z == 0) ? Pq : (z == 1) ? Pk : Pv;
    const float* V    = (z == 0) ? Vq : (z == 1) ? Vk : Vv;
    const float* bias = (z == 0) ? bq : (z == 1) ? bk : bv;
    __nv_bfloat16* dst = (z == 0) ? g_q : (z == 1) ? g_k : g_v;

    const int tid = threadIdx.x;
    const int w = tid >> 5, lane = tid & 31;
    const int g = lane >> 2, tg = lane & 3;
    const int n0 = blockIdx.x * 128;          // 2 heads per CTA
    const int m0 = blockIdx.y * 128;
    const int co = (w >> 2) * 64;             // warp column offset (head select)
    const int wr = (w & 3) * 32;              // warp row offset

    // prologue: chunk 0 into buffer 0
    #pragma unroll
    for (int e = 0; e < 4; e++) {
        int c = e * 256 + tid;
        int row = c >> 3, f = c & 7;
        cp16(sb + PA_OFF + row * 144 + f * 16, P + (size_t)(m0 + row) * RR + f * 4);
    }
    #pragma unroll
    for (int e = 0; e < 4; e++) {
        int c = e * 256 + tid;
        int k = c >> 5, f = c & 31;
        cp16(sb + PB_OFF + k * 528 + f * 16, V + (size_t)k * DD + n0 + f * 4);
    }
    cp_commit();

    float acc[2][8][4];
    #pragma unroll
    for (int gi = 0; gi < 2; gi++)
        #pragma unroll
        for (int j = 0; j < 8; j++)
            #pragma unroll
            for (int c = 0; c < 4; c++) acc[gi][j][c] = 0.0f;

    for (int ch = 0; ch < 8; ch++) {
        const int buf = ch & 1, nb = buf ^ 1;
        if (ch < 7) {
            int k0 = (ch + 1) * 32;
            #pragma unroll
            for (int e = 0; e < 4; e++) {
                int c = e * 256 + tid;
                int row = c >> 3, f = c & 7;
                cp16(sb + PA_OFF + nb * 18432 + row * 144 + f * 16,
                     P + (size_t)(m0 + row) * RR + k0 + f * 4);
            }
            #pragma unroll
            for (int e = 0; e < 4; e++) {
                int c = e * 256 + tid;
                int k = c >> 5, f = c & 31;
                cp16(sb + PB_OFF + nb * 16896 + k * 528 + f * 16,
                     V + (size_t)(k0 + k) * DD + n0 + f * 4);
            }
            cp_commit();
            cp_wait<1>();
        } else {
            cp_wait<0>();
        }
        __syncthreads();

        const float* As  = (const float*)(smem + PA_OFF + buf * 18432);
        const float* Bsm = (const float*)(smem + PB_OFF + buf * 16896);
        #pragma unroll
        for (int s = 0; s < 4; s++) {
            uint32_t a[2][4];
            #pragma unroll
            for (int gi = 0; gi < 2; gi++) {
                int ra = wr + gi * 16 + g;
                a[gi][0] = fbits(As[ra * 36 + 8 * s + tg]);
                a[gi][1] = fbits(As[(ra + 8) * 36 + 8 * s + tg]);
                a[gi][2] = fbits(As[ra * 36 + 8 * s + tg + 4]);
                a[gi][3] = fbits(As[(ra + 8) * 36 + 8 * s + tg + 4]);
            }
            #pragma unroll
            for (int j = 0; j < 8; j++) {
                uint32_t b0 = fbits(Bsm[(8 * s + tg) * 132 + co + 8 * j + g]);
                uint32_t b1 = fbits(Bsm[(8 * s + tg + 4) * 132 + co + 8 * j + g]);
                mma8(acc[0][j], a[0], b0, b1);
                mma8(acc[1][j], a[1], b0, b1);
            }
        }
        __syncthreads();
    }

    if (z == 2) {
        // V: stage 128x128 fp32 (pitch 129) then transposed bf16 store (b,h,dh,m)
        float* stg = (float*)smem;
        #pragma unroll
        for (int gi = 0; gi < 2; gi++) {
            int r0l = wr + gi * 16 + g;
            #pragma unroll
            for (int j = 0; j < 8; j++) {
                int c0 = co + 8 * j + 2 * tg;
                float b0v = bias[n0 + c0], b1v = bias[n0 + c0 + 1];
                stg[r0l * 129 + c0]           = acc[gi][j][0] + b0v;
                stg[r0l * 129 + c0 + 1]       = acc[gi][j][1] + b1v;
                stg[(r0l + 8) * 129 + c0]     = acc[gi][j][2] + b0v;
                stg[(r0l + 8) * 129 + c0 + 1] = acc[gi][j][3] + b1v;
            }
        }
        __syncthreads();
        int c = tid & 127, half = tid >> 7;    // col 0..127, row-half 0/1
        int bb = m0 >> 11, mloc = m0 & (MM - 1);
        int hcol = blockIdx.x * 2 + (c >> 6);
        int dh = c & 63;
        __nv_bfloat16* o = g_v + ((size_t)(bb * HH + hcol) * DHH + dh) * MM + mloc + half * 64;
        #pragma unroll
        for (int e = 0; e < 8; e++) {
            int rb = half * 64 + e * 8;
            uint4 wv;
            wv.x = bf2(stg[rb * 129 + c],       stg[(rb + 1) * 129 + c]);
            wv.y = bf2(stg[(rb + 2) * 129 + c], stg[(rb + 3) * 129 + c]);
            wv.z = bf2(stg[(rb + 4) * 129 + c], stg[(rb + 5) * 129 + c]);
            wv.w = bf2(stg[(rb + 6) * 129 + c], stg[(rb + 7) * 129 + c]);
            *(uint4*)(o + e * 8) = wv;
        }
    } else {
        // q/k: bias + RoPE (table) + bf16 store; warp owns head h
        const int h = blockIdx.x * 2 + (w >> 2);
        const int n0h = h * 64;
        float bl[4][4];
        #pragma unroll
        for (int jlo = 0; jlo < 4; jlo++) {
            int c0 = 8 * jlo + 2 * tg;
            bl[jlo][0] = bias[n0h + c0];
            bl[jlo][1] = bias[n0h + c0 + 1];
            bl[jlo][2] = bias[n0h + c0 + 32];
            bl[jlo][3] = bias[n0h + c0 + 33];
        }
        #pragma unroll
        for (int gi = 0; gi < 2; gi++) {
            int rbase = m0 + wr + gi * 16 + g;
            #pragma unroll
            for (int hh = 0; hh < 2; hh++) {
                int row = rbase + 8 * hh;
                int iA = 2 * hh;
                int bb = row >> 11, mloc = row & (MM - 1);
                const float* cs = g_cs + (size_t)row * 64;
                __nv_bfloat16* o = dst + ((size_t)(bb * HH + h) * MM + mloc) * DHH;
                #pragma unroll
                for (int jlo = 0; jlo < 4; jlo++) {
                    int c0 = 8 * jlo + 2 * tg;
                    float x0a = acc[gi][jlo][iA]         + bl[jlo][0];
                    float x0b = acc[gi][jlo][iA + 1]     + bl[jlo][1];
                    float x1a = acc[gi][jlo + 4][iA]     + bl[jlo][2];
                    float x1b = acc[gi][jlo + 4][iA + 1] + bl[jlo][3];
                    float2 cp = *(const float2*)&cs[c0];
                    float2 sp = *(const float2*)&cs[32 + c0];
                    *(__nv_bfloat162*)&o[c0] =
                        __floats2bfloat162_rn(x0a * cp.x - x1a * sp.x, x0b * cp.y - x1b * sp.y);
                    *(__nv_bfloat162*)&o[c0 + 32] =
                        __floats2bfloat162_rn(x0a * sp.x + x1a * cp.x, x0b * sp.y + x1b * cp.y);
                }
            }
        }
    }
}

// ---------------------------------------------------------------------------
// Attention: R12 base with ONE change — Q fragments hoisted into registers
// (loaded once via ldmatrix after the prologue; reg ceiling is 256/thread at
// 2 CTAs/SM x 128 thr, so the +32 regs are free).
// Smem: Q 18432 | K 2x9216 | Vt 2x9216 | mask 2x256 | maskf 2x256 -> 56320 B
// ---------------------------------------------------------------------------
#define Q_OFF    0
#define K_OFF    18432
#define V_OFF    36864
#define MSK_OFF  55296
#define MSKF_OFF 55808
#define SMEM_TOTAL 56320
#define KV_STRIDE 9216
#define PITCHB 144   // 72 bf16 = 144 bytes per row

__global__ __launch_bounds__(128, 2) void attn_kernel(const int* __restrict__ amask,
                                                      float* __restrict__ out)
{
    extern __shared__ char smem[];
    const uint32_t sb = smem_u32(smem);

    const int tid = threadIdx.x;
    const int w = tid >> 5, lane = tid & 31;
    const int g = lane >> 2, tg = lane & 3;
    const int bh = blockIdx.x;
    const int b = bh >> 4;
    const int m0 = blockIdx.y * 128;

    const float C1 = 0.18033688011112042f;   // (1/8)*log2(e)
    const float C2 = 43.28085122666891f;     // 30*log2(e)

    const __nv_bfloat16* qg = g_q + ((size_t)bh * MM + m0) * DHH;
    const __nv_bfloat16* kg = g_k + (size_t)bh * MM * DHH;
    const __nv_bfloat16* vg = g_v + (size_t)bh * DHH * MM;

    // ---- prologue: Q (128x64), K block0, Vt block0, mask0 ----
    #pragma unroll
    for (int e = 0; e < 8; e++) {
        int c = e * 128 + tid;
        int row = c >> 3, f = c & 7;
        cp16(sb + Q_OFF + row * PITCHB + f * 16, qg + row * 64 + f * 8);
    }
    #pragma unroll
    for (int e = 0; e < 4; e++) {
        int c = e * 128 + tid;
        int row = c >> 3, f = c & 7;
        cp16(sb + K_OFF + row * PITCHB + f * 16, kg + (size_t)row * 64 + f * 8);
        cp16(sb + V_OFF + row * PITCHB + f * 16, vg + (size_t)row * MM + f * 8);
    }
    if (tid < 16) cp16(sb + MSK_OFF + tid * 16, amask + (size_t)b * MM + tid * 4);
    cp_commit();
    cp_wait<0>();
    __syncthreads();
    // mask block0 -> float addend
    if (tid < 64) {
        int mraw = ((const int*)(smem + MSK_OFF))[tid];
        ((float*)(smem + MSKF_OFF))[tid] = mraw ? -C2 : -1e30f;
    }
    __syncthreads();

    // ---- ldmatrix per-thread base offsets ----
    const int lrow = lane & 7, lsel = lane >> 3;
    const uint32_t qbase = sb + Q_OFF
        + (uint32_t)(w * 32 + lrow + (lsel & 1) * 8) * PITCHB + (lsel >> 1) * 16;
    const uint32_t bboff = (uint32_t)(lrow + (lsel >> 1) * 8) * PITCHB + (lsel & 1) * 16;

    // ---- Q A-fragments: loop-invariant, loaded ONCE ----
    uint32_t qa[4][2][4];
    #pragma unroll
    for (int s = 0; s < 4; s++) {
        ldm4(qa[s][0][0], qa[s][0][1], qa[s][0][2], qa[s][0][3], qbase + s * 32);
        ldm4(qa[s][1][0], qa[s][1][1], qa[s][1][2], qa[s][1][3], qbase + 16 * PITCHB + s * 32);
    }

    float oc[2][8][4];
    #pragma unroll
    for (int gi = 0; gi < 2; gi++)
        #pragma unroll
        for (int j = 0; j < 8; j++)
            #pragma unroll
            for (int c = 0; c < 4; c++) oc[gi][j][c] = 0.0f;
    float ls[2][2] = {{0.f, 0.f}, {0.f, 0.f}};

    const int row0 = w * 32;

    for (int i = 0; i < 32; i++) {
        const int buf = i & 1, nb = buf ^ 1;

        if (i < 31) {
            int n1 = (i + 1) * 64;
            #pragma unroll
            for (int e = 0; e < 4; e++) {
                int c = e * 128 + tid;
                int row = c >> 3, f = c & 7;
                cp16(sb + K_OFF + nb * KV_STRIDE + row * PITCHB + f * 16,
                     kg + (size_t)(n1 + row) * 64 + f * 8);
                cp16(sb + V_OFF + nb * KV_STRIDE + row * PITCHB + f * 16,
                     vg + (size_t)row * MM + n1 + f * 8);
            }
            if (tid < 16) cp16(sb + MSK_OFF + nb * 256 + tid * 16,
                               amask + (size_t)b * MM + n1 + tid * 4);
            cp_commit();
        }

        const uint32_t kb = sb + K_OFF + buf * KV_STRIDE + bboff;
        const uint32_t vb = sb + V_OFF + buf * KV_STRIDE + bboff;
        const float* mskf = (const float*)(smem + MSKF_OFF + buf * 256);

        // ---- S = Q(32 rows) x K^T(64 keys); K frags via ldmatrix ----
        float sc[2][8][4];
        #pragma unroll
        for (int gi = 0; gi < 2; gi++)
            #pragma unroll
            for (int j = 0; j < 8; j++)
                #pragma unroll
                for (int c = 0; c < 4; c++) sc[gi][j][c] = 0.0f;

        #pragma unroll
        for (int s = 0; s < 4; s++) {
            #pragma unroll
            for (int jp = 0; jp < 4; jp++) {
                uint32_t b0, b1, b2, b3;
                ldm4(b0, b1, b2, b3, kb + jp * (16 * PITCHB) + s * 32);
                mmab(sc[0][2 * jp],     qa[s][0], b0, b1);
                mmab(sc[1][2 * jp],     qa[s][1], b0, b1);
                mmab(sc[0][2 * jp + 1], qa[s][0], b2, b3);
                mmab(sc[1][2 * jp + 1], qa[s][1], b2, b3);
            }
        }

        // ---- softmax: p = ex2(fma(s, C1, maskf)); pack into A-frags ----
        uint32_t pa[2][4][4];
        #pragma unroll
        for (int j = 0; j < 8; j++) {
            float2 mf = *(const float2*)&mskf[8 * j + 2 * tg];
            #pragma unroll
            for (int gi = 0; gi < 2; gi++) {
                float p0 = ex2f(fmaf(sc[gi][j][0], C1, mf.x));
                float p1 = ex2f(fmaf(sc[gi][j][1], C1, mf.y));
                float p2 = ex2f(fmaf(sc[gi][j][2], C1, mf.x));
                float p3 = ex2f(fmaf(sc[gi][j][3], C1, mf.y));
                ls[gi][0] += p0 + p1;
                ls[gi][1] += p2 + p3;
                int s = j >> 1;
                if ((j & 1) == 0) {
                    pa[gi][s][0] = bf2(p0, p1);
                    pa[gi][s][1] = bf2(p2, p3);
                } else {
                    pa[gi][s][2] = bf2(p0, p1);
                    pa[gi][s][3] = bf2(p2, p3);
                }
            }
        }

        // ---- O += P x V (B frags via ldmatrix) ----
        #pragma unroll
        for (int s = 0; s < 4; s++) {
            #pragma unroll
            for (int jp = 0; jp < 4; jp++) {
                uint32_t b0, b1, b2, b3;
                ldm4(b0, b1, b2, b3, vb + jp * (16 * PITCHB) + s * 32);
                mmab(oc[0][2 * jp],     pa[0][s], b0, b1);
                mmab(oc[1][2 * jp],     pa[1][s], b0, b1);
                mmab(oc[0][2 * jp + 1], pa[0][s], b2, b3);
                mmab(oc[1][2 * jp + 1], pa[1][s], b2, b3);
            }
        }

        cp_wait<0>();
        // convert next mask block (its cp.async completed just above)
        if (i < 31 && tid < 64) {
            int mraw = ((const int*)(smem + MSK_OFF + nb * 256))[tid];
            ((float*)(smem + MSKF_OFF + nb * 256))[tid] = mraw ? -C2 : -1e30f;
        }
        __syncthreads();
    }

    // ---- finalize ----
    #pragma unroll
    for (int gi = 0; gi < 2; gi++) {
        float l0 = ls[gi][0];
        l0 += __shfl_xor_sync(0xffffffffu, l0, 1);
        l0 += __shfl_xor_sync(0xffffffffu, l0, 2);
        float l1 = ls[gi][1];
        l1 += __shfl_xor_sync(0xffffffffu, l1, 1);
        l1 += __shfl_xor_sync(0xffffffffu, l1, 2);
        float i0 = (l0 > 0.f) ? (1.0f / l0) : 0.f;
        float i1 = (l1 > 0.f) ? (1.0f / l1) : 0.f;
        int row = row0 + gi * 16 + g;
        float* o0 = out + ((size_t)bh * MM + m0 + row) * DHH;
        float* o1 = out + ((size_t)bh * MM + m0 + row + 8) * DHH;
        #pragma unroll
        for (int j = 0; j < 8; j++) {
            *(float2*)(o0 + 8 * j + 2 * tg) = make_float2(oc[gi][j][0] * i0, oc[gi][j][1] * i0);
            *(float2*)(o1 + 8 * j + 2 * tg) = make_float2(oc[gi][j][2] * i1, oc[gi][j][3] * i1);
        }
    }
}

extern "C" void kernel_launch(void* const* d_in, const int* in_sizes, int n_in,
                              void* d_out, int out_size) {
    const float* Pq = (const float*)d_in[0];
    const float* Pk = (const float*)d_in[1];
    const float* Pv = (const float*)d_in[2];
    const float* Vq = (const float*)d_in[3];
    const float* Vk = (const float*)d_in[4];
    const float* Vv = (const float*)d_in[5];
    const float* bq = (const float*)d_in[6];
    const float* bk = (const float*)d_in[7];
    const float* bv = (const float*)d_in[8];
    const int* amask = (const int*)d_in[9];
    const int* pos   = (const int*)d_in[10];

    static int smem_set = 0;
    if (!smem_set) {
        cudaFuncSetAttribute(attn_kernel, cudaFuncAttributeMaxDynamicSharedMemorySize, SMEM_TOTAL);
        cudaFuncSetAttribute(proj_kernel, cudaFuncAttributeMaxDynamicSharedMemorySize, PROJ_SMEM);
        smem_set = 1;
    }

    rope_kernel<<<BB * MM * 32 / 256, 256>>>(pos);

    dim3 pg(HH / 2, (BB * MM) / 128, 3);     // 8 x 32 x 3
    proj_kernel<<<pg, 256, PROJ_SMEM>>>(Pq, Pk, Pv, Vq, Vk, Vv, bq, bk, bv);

    dim3 ag(BB * HH, MM / 128);              // 32 x 16
    attn_kernel<<<ag, 128, SMEM_TOTAL>>>(amask, (float*)d_out);
}

// round 16
// speedup vs baseline: 1.0609x; 1.0154x over previous
#include <cuda_runtime.h>
#include <cuda_bf16.h>
#include <cstdint>

#define BB 2
#define MM 2048
#define RR 256
#define HH 16
#define DHH 64
#define DD (HH*DHH)

// Scratch (bf16): q,k in (b,h,m,dh); v TRANSPOSED in (b,h,dh,m).
__device__ __align__(128) __nv_bfloat16 g_q[BB*HH*MM*DHH];
__device__ __align__(128) __nv_bfloat16 g_k[BB*HH*MM*DHH];
__device__ __align__(128) __nv_bfloat16 g_v[BB*HH*MM*DHH];
// RoPE table: per (b*M+m) row, 32 cos then 32 sin.
__device__ __align__(128) float g_cs[BB*MM*64];

// ---------------- misc helpers ----------------
__device__ __forceinline__ uint32_t smem_u32(const void* p) {
    uint32_t a;
    asm("{ .reg .u64 t; cvta.to.shared.u64 t, %1; cvt.u32.u64 %0, t; }" : "=r"(a) : "l"(p));
    return a;
}
__device__ __forceinline__ void cp16(uint32_t dst, const void* src) {
    asm volatile("cp.async.cg.shared.global [%0], [%1], 16;" :: "r"(dst), "l"(src) : "memory");
}
__device__ __forceinline__ void cp_commit() { asm volatile("cp.async.commit_group;" ::: "memory"); }
template <int N>
__device__ __forceinline__ void cp_wait() { asm volatile("cp.async.wait_group %0;" :: "n"(N) : "memory"); }
__device__ __forceinline__ float ex2f(float x) {
    float r;
    asm("ex2.approx.ftz.f32 %0, %1;" : "=f"(r) : "f"(x));
    return r;
}
__device__ __forceinline__ uint32_t bf2(float lo, float hi) {
    __nv_bfloat162 t = __floats2bfloat162_rn(lo, hi);
    return *(uint32_t*)&t;
}
__device__ __forceinline__ uint32_t fbits(float x) { return __float_as_uint(x); }

// m16n8k16 bf16 warp MMA
__device__ __forceinline__ void mmab(float* c, const uint32_t* a, uint32_t b0, uint32_t b1) {
    asm volatile("mma.sync.aligned.m16n8k16.row.col.f32.bf16.bf16.f32 "
        "{%0,%1,%2,%3}, {%4,%5,%6,%7}, {%8,%9}, {%0,%1,%2,%3};"
        : "+f"(c[0]), "+f"(c[1]), "+f"(c[2]), "+f"(c[3])
        : "r"(a[0]), "r"(a[1]), "r"(a[2]), "r"(a[3]), "r"(b0), "r"(b1));
}
// m16n8k8 tf32 warp MMA
__device__ __forceinline__ void mma8(float* c, const uint32_t* a, uint32_t b0, uint32_t b1) {
    asm volatile("mma.sync.aligned.m16n8k8.row.col.f32.tf32.tf32.f32 "
        "{%0,%1,%2,%3}, {%4,%5,%6,%7}, {%8,%9}, {%0,%1,%2,%3};"
        : "+f"(c[0]), "+f"(c[1]), "+f"(c[2]), "+f"(c[3])
        : "r"(a[0]), "r"(a[1]), "r"(a[2]), "r"(a[3]), "r"(b0), "r"(b1));
}
// ldmatrix x4 (sm_75+)
__device__ __forceinline__ void ldm4(uint32_t& r0, uint32_t& r1, uint32_t& r2, uint32_t& r3,
                                     uint32_t addr) {
    asm volatile("ldmatrix.sync.aligned.m8n8.x4.shared.b16 {%0,%1,%2,%3}, [%4];"
        : "=r"(r0), "=r"(r1), "=r"(r2), "=r"(r3) : "r"(addr));
}

// ---------------------------------------------------------------------------
// RoPE table kernel
// ---------------------------------------------------------------------------
__global__ __launch_bounds__(256) void rope_kernel(const int* __restrict__ pos_ids) {
    int idx = blockIdx.x * 256 + threadIdx.x;
    int f = idx & 31, row = idx >> 5;
    float p = (float)pos_ids[row];
    float inv = exp2f(-(float)f * 0.41524101186092033f);
    float s, c;
    sincosf(p * inv, &s, &c);
    g_cs[row * 64 + f] = c;
    g_cs[row * 64 + 32 + f] = s;
}

// ---------------------------------------------------------------------------
// Projection via tf32 mma.sync: 128x128 tile (2 heads) per CTA, 256 threads
// (exact R15 version).
// ---------------------------------------------------------------------------
#define PA_OFF 0
#define PB_OFF 36864
#define PROJ_SMEM 70656

__global__ __launch_bounds__(256) void proj_kernel(
    const float* __restrict__ Pq, const float* __restrict__ Pk, const float* __restrict__ Pv,
    const float* __restrict__ Vq, const float* __restrict__ Vk, const float* __restrict__ Vv,
    const float* __restrict__ bq, const float* __restrict__ bk, const float* __restrict__ bv)
{
    extern __shared__ char smem[];
    const uint32_t sb = smem_u32(smem);

    const int z = blockIdx.z;
    const float* P    = (z == 0) ? Pq : (z == 1) ? Pk : Pv;
    const float* V    = (z == 0) ? Vq : (z == 1) ? Vk : Vv;
    const float* bias = (z == 0) ? bq : (z == 1) ? bk : bv;
    __nv_bfloat16* dst = (z == 0) ? g_q : (z == 1) ? g_k : g_v;

    const int tid = threadIdx.x;
    const int w = tid >> 5, lane = tid & 31;
    const int g = lane >> 2, tg = lane & 3;
    const int n0 = blockIdx.x * 128;          // 2 heads per CTA
    const int m0 = blockIdx.y * 128;
    const int co = (w >> 2) * 64;             // warp column offset (head select)
    const int wr = (w & 3) * 32;              // warp row offset

    // prologue: chunk 0 into buffer 0
    #pragma unroll
    for (int e = 0; e < 4; e++) {
        int c = e * 256 + tid;
        int row = c >> 3, f = c & 7;
        cp16(sb + PA_OFF + row * 144 + f * 16, P + (size_t)(m0 + row) * RR + f * 4);
    }
    #pragma unroll
    for (int e = 0; e < 4; e++) {
        int c = e * 256 + tid;
        int k = c >> 5, f = c & 31;
        cp16(sb + PB_OFF + k * 528 + f * 16, V + (size_t)k * DD + n0 + f * 4);
    }
    cp_commit();

    float acc[2][8][4];
    #pragma unroll
    for (int gi = 0; gi < 2; gi++)
        #pragma unroll
        for (int j = 0; j < 8; j++)
            #pragma unroll
            for (int c = 0; c < 4; c++) acc[gi][j][c] = 0.0f;

    for (int ch = 0; ch < 8; ch++) {
        const int buf = ch & 1, nb = buf ^ 1;
        if (ch < 7) {
            int k0 = (ch + 1) * 32;
            #pragma unroll
            for (int e = 0; e < 4; e++) {
                int c = e * 256 + tid;
                int row = c >> 3, f = c & 7;
                cp16(sb + PA_OFF + nb * 18432 + row * 144 + f * 16,
                     P + (size_t)(m0 + row) * RR + k0 + f * 4);
            }
            #pragma unroll
            for (int e = 0; e < 4; e++) {
                int c = e * 256 + tid;
                int k = c >> 5, f = c & 31;
                cp16(sb + PB_OFF + nb * 16896 + k * 528 + f * 16,
                     V + (size_t)(k0 + k) * DD + n0 + f * 4);
            }
            cp_commit();
            cp_wait<1>();
        } else {
            cp_wait<0>();
        }
        __syncthreads();

        const float* As  = (const float*)(smem + PA_OFF + buf * 18432);
        const float* Bsm = (const float*)(smem + PB_OFF + buf * 16896);
        #pragma unroll
        for (int s = 0; s < 4; s++) {
            uint32_t a[2][4];
            #pragma unroll
            for (int gi = 0; gi < 2; gi++) {
                int ra = wr + gi * 16 + g;
                a[gi][0] = fbits(As[ra * 36 + 8 * s + tg]);
                a[gi][1] = fbits(As[(ra + 8) * 36 + 8 * s + tg]);
                a[gi][2] = fbits(As[ra * 36 + 8 * s + tg + 4]);
                a[gi][3] = fbits(As[(ra + 8) * 36 + 8 * s + tg + 4]);
            }
            #pragma unroll
            for (int j = 0; j < 8; j++) {
                uint32_t b0 = fbits(Bsm[(8 * s + tg) * 132 + co + 8 * j + g]);
                uint32_t b1 = fbits(Bsm[(8 * s + tg + 4) * 132 + co + 8 * j + g]);
                mma8(acc[0][j], a[0], b0, b1);
                mma8(acc[1][j], a[1], b0, b1);
            }
        }
        __syncthreads();
    }

    if (z == 2) {
        // V: stage 128x128 fp32 (pitch 129) then transposed bf16 store (b,h,dh,m)
        float* stg = (float*)smem;
        #pragma unroll
        for (int gi = 0; gi < 2; gi++) {
            int r0l = wr + gi * 16 + g;
            #pragma unroll
            for (int j = 0; j < 8; j++) {
                int c0 = co + 8 * j + 2 * tg;
                float b0v = bias[n0 + c0], b1v = bias[n0 + c0 + 1];
                stg[r0l * 129 + c0]           = acc[gi][j][0] + b0v;
                stg[r0l * 129 + c0 + 1]       = acc[gi][j][1] + b1v;
                stg[(r0l + 8) * 129 + c0]     = acc[gi][j][2] + b0v;
                stg[(r0l + 8) * 129 + c0 + 1] = acc[gi][j][3] + b1v;
            }
        }
        __syncthreads();
        int c = tid & 127, half = tid >> 7;    // col 0..127, row-half 0/1
        int bb = m0 >> 11, mloc = m0 & (MM - 1);
        int hcol = blockIdx.x * 2 + (c >> 6);
        int dh = c & 63;
        __nv_bfloat16* o = g_v + ((size_t)(bb * HH + hcol) * DHH + dh) * MM + mloc + half * 64;
        #pragma unroll
        for (int e = 0; e < 8; e++) {
            int rb = half * 64 + e * 8;
            uint4 wv;
            wv.x = bf2(stg[rb * 129 + c],       stg[(rb + 1) * 129 + c]);
            wv.y = bf2(stg[(rb + 2) * 129 + c], stg[(rb + 3) * 129 + c]);
            wv.z = bf2(stg[(rb + 4) * 129 + c], stg[(rb + 5) * 129 + c]);
            wv.w = bf2(stg[(rb + 6) * 129 + c], stg[(rb + 7) * 129 + c]);
            *(uint4*)(o + e * 8) = wv;
        }
    } else {
        // q/k: bias + RoPE (table) + bf16 store; warp owns head h
        const int h = blockIdx.x * 2 + (w >> 2);
        const int n0h = h * 64;
        float bl[4][4];
        #pragma unroll
        for (int jlo = 0; jlo < 4; jlo++) {
            int c0 = 8 * jlo + 2 * tg;
            bl[jlo][0] = bias[n0h + c0];
            bl[jlo][1] = bias[n0h + c0 + 1];
            bl[jlo][2] = bias[n0h + c0 + 32];
            bl[jlo][3] = bias[n0h + c0 + 33];
        }
        #pragma unroll
        for (int gi = 0; gi < 2; gi++) {
            int rbase = m0 + wr + gi * 16 + g;
            #pragma unroll
            for (int hh = 0; hh < 2; hh++) {
                int row = rbase + 8 * hh;
                int iA = 2 * hh;
                int bb = row >> 11, mloc = row & (MM - 1);
                const float* cs = g_cs + (size_t)row * 64;
                __nv_bfloat16* o = dst + ((size_t)(bb * HH + h) * MM + mloc) * DHH;
                #pragma unroll
                for (int jlo = 0; jlo < 4; jlo++) {
                    int c0 = 8 * jlo + 2 * tg;
                    float x0a = acc[gi][jlo][iA]         + bl[jlo][0];
                    float x0b = acc[gi][jlo][iA + 1]     + bl[jlo][1];
                    float x1a = acc[gi][jlo + 4][iA]     + bl[jlo][2];
                    float x1b = acc[gi][jlo + 4][iA + 1] + bl[jlo][3];
                    float2 cp = *(const float2*)&cs[c0];
                    float2 sp = *(const float2*)&cs[32 + c0];
                    *(__nv_bfloat162*)&o[c0] =
                        __floats2bfloat162_rn(x0a * cp.x - x1a * sp.x, x0b * cp.y - x1b * sp.y);
                    *(__nv_bfloat162*)&o[c0 + 32] =
                        __floats2bfloat162_rn(x0a * sp.x + x1a * cp.x, x0b * sp.y + x1b * cp.y);
                }
            }
        }
    }
}

// ---------------------------------------------------------------------------
// Attention: R15 base + (a) whole mask row precomputed to float addends in
// the prologue (8 KB smem, no per-iter mask work), (b) 4-buffer K/V ring with
// prefetch distance 2 -> cp_wait + __syncthreads only on EVEN iterations
// (ring reuse gap is 2 iters; the even-top wait<0>+sync covers blocks i and
// i+1 for visibility and all WAR hazards).
// Smem: Q 18432 | K 4x9216 | Vt 4x9216 | maskf 8192 -> 100352 B; 2 CTAs/SM.
// ---------------------------------------------------------------------------
#define Q_OFF    0
#define K_OFF    18432
#define V_OFF    55296
#define MSKF_OFF 92160
#define SMEM_TOTAL 100352
#define KV_STRIDE 9216
#define PITCHB 144   // 72 bf16 = 144 bytes per row

__global__ __launch_bounds__(128, 2) void attn_kernel(const int* __restrict__ amask,
                                                      float* __restrict__ out)
{
    extern __shared__ char smem[];
    const uint32_t sb = smem_u32(smem);

    const int tid = threadIdx.x;
    const int w = tid >> 5, lane = tid & 31;
    const int g = lane >> 2, tg = lane & 3;
    const int bh = blockIdx.x;
    const int b = bh >> 4;
    const int m0 = blockIdx.y * 128;

    const float C1 = 0.18033688011112042f;   // (1/8)*log2(e)
    const float C2 = 43.28085122666891f;     // 30*log2(e)

    const __nv_bfloat16* qg = g_q + ((size_t)bh * MM + m0) * DHH;
    const __nv_bfloat16* kg = g_k + (size_t)bh * MM * DHH;
    const __nv_bfloat16* vg = g_v + (size_t)bh * DHH * MM;

    // ---- prologue group 0: Q (128x64) + K0/V0 ----
    #pragma unroll
    for (int e = 0; e < 8; e++) {
        int c = e * 128 + tid;
        int row = c >> 3, f = c & 7;
        cp16(sb + Q_OFF + row * PITCHB + f * 16, qg + row * 64 + f * 8);
    }
    #pragma unroll
    for (int e = 0; e < 4; e++) {
        int c = e * 128 + tid;
        int row = c >> 3, f = c & 7;
        cp16(sb + K_OFF + row * PITCHB + f * 16, kg + (size_t)row * 64 + f * 8);
        cp16(sb + V_OFF + row * PITCHB + f * 16, vg + (size_t)row * MM + f * 8);
    }
    cp_commit();
    // ---- prologue group 1: K1/V1 ----
    #pragma unroll
    for (int e = 0; e < 4; e++) {
        int c = e * 128 + tid;
        int row = c >> 3, f = c & 7;
        cp16(sb + K_OFF + KV_STRIDE + row * PITCHB + f * 16,
             kg + (size_t)(64 + row) * 64 + f * 8);
        cp16(sb + V_OFF + KV_STRIDE + row * PITCHB + f * 16,
             vg + (size_t)row * MM + 64 + f * 8);
    }
    cp_commit();
    // ---- prologue group 2: whole mask row (2048 ints = 8 KB) ----
    #pragma unroll
    for (int e = 0; e < 4; e++) {
        int c = e * 128 + tid;
        cp16(sb + MSKF_OFF + c * 16, amask + (size_t)b * MM + c * 4);
    }
    cp_commit();
    cp_wait<0>();
    __syncthreads();
    // in-place convert int mask -> float addend (each thread owns 16 slots)
    {
        float* mf = (float*)(smem + MSKF_OFF);
        const int* mi = (const int*)(smem + MSKF_OFF);
        #pragma unroll
        for (int e = 0; e < 16; e++) {
            int idx = e * 128 + tid;
            int mraw = mi[idx];
            mf[idx] = mraw ? -C2 : -1e30f;
        }
    }
    __syncthreads();

    // ---- ldmatrix per-thread base offsets ----
    const int lrow = lane & 7, lsel = lane >> 3;
    const uint32_t qbase = sb + Q_OFF
        + (uint32_t)(w * 32 + lrow + (lsel & 1) * 8) * PITCHB + (lsel >> 1) * 16;
    const uint32_t bboff = (uint32_t)(lrow + (lsel >> 1) * 8) * PITCHB + (lsel & 1) * 16;

    // ---- Q A-fragments: loop-invariant, loaded ONCE ----
    uint32_t qa[4][2][4];
    #pragma unroll
    for (int s = 0; s < 4; s++) {
        ldm4(qa[s][0][0], qa[s][0][1], qa[s][0][2], qa[s][0][3], qbase + s * 32);
        ldm4(qa[s][1][0], qa[s][1][1], qa[s][1][2], qa[s][1][3], qbase + 16 * PITCHB + s * 32);
    }

    float oc[2][8][4];
    #pragma unroll
    for (int gi = 0; gi < 2; gi++)
        #pragma unroll
        for (int j = 0; j < 8; j++)
            #pragma unroll
            for (int c = 0; c < 4; c++) oc[gi][j][c] = 0.0f;
    float ls[2][2] = {{0.f, 0.f}, {0.f, 0.f}};

    const int row0 = w * 32;

    for (int i = 0; i < 32; i++) {
        // even-iteration top: wait all cp groups, one barrier covering the
        // next two iterations' reads and all ring-reuse WAR hazards.
        if ((i & 1) == 0) {
            cp_wait<0>();
            __syncthreads();
        }

        // prefetch block i+2 into ring slot (i+2)&3
        if (i < 30) {
            int n1 = (i + 2) * 64;
            uint32_t koff = sb + K_OFF + ((i + 2) & 3) * KV_STRIDE;
            uint32_t voff = sb + V_OFF + ((i + 2) & 3) * KV_STRIDE;
            #pragma unroll
            for (int e = 0; e < 4; e++) {
                int c = e * 128 + tid;
                int row = c >> 3, f = c & 7;
                cp16(koff + row * PITCHB + f * 16, kg + (size_t)(n1 + row) * 64 + f * 8);
                cp16(voff + row * PITCHB + f * 16, vg + (size_t)row * MM + n1 + f * 8);
            }
            cp_commit();
        }

        const uint32_t kb = sb + K_OFF + (i & 3) * KV_STRIDE + bboff;
        const uint32_t vb = sb + V_OFF + (i & 3) * KV_STRIDE + bboff;
        const float* mskf = (const float*)(smem + MSKF_OFF) + i * 64;

        // ---- S = Q(32 rows) x K^T(64 keys); K frags via ldmatrix ----
        float sc[2][8][4];
        #pragma unroll
        for (int gi = 0; gi < 2; gi++)
            #pragma unroll
            for (int j = 0; j < 8; j++)
                #pragma unroll
                for (int c = 0; c < 4; c++) sc[gi][j][c] = 0.0f;

        #pragma unroll
        for (int s = 0; s < 4; s++) {
            #pragma unroll
            for (int jp = 0; jp < 4; jp++) {
                uint32_t b0, b1, b2, b3;
                ldm4(b0, b1, b2, b3, kb + jp * (16 * PITCHB) + s * 32);
                mmab(sc[0][2 * jp],     qa[s][0], b0, b1);
                mmab(sc[1][2 * jp],     qa[s][1], b0, b1);
                mmab(sc[0][2 * jp + 1], qa[s][0], b2, b3);
                mmab(sc[1][2 * jp + 1], qa[s][1], b2, b3);
            }
        }

        // ---- softmax: p = ex2(fma(s, C1, maskf)); pack into A-frags ----
        uint32_t pa[2][4][4];
        #pragma unroll
        for (int j = 0; j < 8; j++) {
            float2 mf = *(const float2*)&mskf[8 * j + 2 * tg];
            #pragma unroll
            for (int gi = 0; gi < 2; gi++) {
                float p0 = ex2f(fmaf(sc[gi][j][0], C1, mf.x));
                float p1 = ex2f(fmaf(sc[gi][j][1], C1, mf.y));
                float p2 = ex2f(fmaf(sc[gi][j][2], C1, mf.x));
                float p3 = ex2f(fmaf(sc[gi][j][3], C1, mf.y));
                ls[gi][0] += p0 + p1;
                ls[gi][1] += p2 + p3;
                int s = j >> 1;
                if ((j & 1) == 0) {
                    pa[gi][s][0] = bf2(p0, p1);
                    pa[gi][s][1] = bf2(p2, p3);
                } else {
                    pa[gi][s][2] = bf2(p0, p1);
                    pa[gi][s][3] = bf2(p2, p3);
                }
            }
        }

        // ---- O += P x V (B frags via ldmatrix) ----
        #pragma unroll
        for (int s = 0; s < 4; s++) {
            #pragma unroll
            for (int jp = 0; jp < 4; jp++) {
                uint32_t b0, b1, b2, b3;
                ldm4(b0, b1, b2, b3, vb + jp * (16 * PITCHB) + s * 32);
                mmab(oc[0][2 * jp],     pa[0][s], b0, b1);
                mmab(oc[1][2 * jp],     pa[1][s], b0, b1);
                mmab(oc[0][2 * jp + 1], pa[0][s], b2, b3);
                mmab(oc[1][2 * jp + 1], pa[1][s], b2, b3);
            }
        }
    }

    // ---- finalize ----
    #pragma unroll
    for (int gi = 0; gi < 2; gi++) {
        float l0 = ls[gi][0];
        l0 += __shfl_xor_sync(0xffffffffu, l0, 1);
        l0 += __shfl_xor_sync(0xffffffffu, l0, 2);
        float l1 = ls[gi][1];
        l1 += __shfl_xor_sync(0xffffffffu, l1, 1);
        l1 += __shfl_xor_sync(0xffffffffu, l1, 2);
        float i0 = (l0 > 0.f) ? (1.0f / l0) : 0.f;
        float i1 = (l1 > 0.f) ? (1.0f / l1) : 0.f;
        int row = row0 + gi * 16 + g;
        float* o0 = out + ((size_t)bh * MM + m0 + row) * DHH;
        float* o1 = out + ((size_t)bh * MM + m0 + row + 8) * DHH;
        #pragma unroll
        for (int j = 0; j < 8; j++) {
            *(float2*)(o0 + 8 * j + 2 * tg) = make_float2(oc[gi][j][0] * i0, oc[gi][j][1] * i0);
            *(float2*)(o1 + 8 * j + 2 * tg) = make_float2(oc[gi][j][2] * i1, oc[gi][j][3] * i1);
        }
    }
}

extern "C" void kernel_launch(void* const* d_in, const int* in_sizes, int n_in,
                              void* d_out, int out_size) {
    const float* Pq = (const float*)d_in[0];
    const float* Pk = (const float*)d_in[1];
    const float* Pv = (const float*)d_in[2];
    const float* Vq = (const float*)d_in[3];
    const float* Vk = (const float*)d_in[4];
    const float* Vv = (const float*)d_in[5];
    const float* bq = (const float*)d_in[6];
    const float* bk = (const float*)d_in[7];
    const float* bv = (const float*)d_in[8];
    const int* amask = (const int*)d_in[9];
    const int* pos   = (const int*)d_in[10];

    static int smem_set = 0;
    if (!smem_set) {
        cudaFuncSetAttribute(attn_kernel, cudaFuncAttributeMaxDynamicSharedMemorySize, SMEM_TOTAL);
        cudaFuncSetAttribute(proj_kernel, cudaFuncAttributeMaxDynamicSharedMemorySize, PROJ_SMEM);
        smem_set = 1;
    }

    rope_kernel<<<BB * MM * 32 / 256, 256>>>(pos);

    dim3 pg(HH / 2, (BB * MM) / 128, 3);     // 8 x 32 x 3
    proj_kernel<<<pg, 256, PROJ_SMEM>>>(Pq, Pk, Pv, Vq, Vk, Vv, bq, bk, bv);

    dim3 ag(BB * HH, MM / 128);              // 32 x 16
    attn_kernel<<<ag, 128, SMEM_TOTAL>>>(amask, (float*)d_out);
}